// round 4
// baseline (speedup 1.0000x reference)
#include <cuda_runtime.h>
#include <math.h>

// AbsPosSelfAttention: q,k,v [2,8,64,64,32] fp32; emb_h,emb_w [64,32].
// out [2,64,64, 8*32] fp32  (out[b][h][w][n*32+d]).
//
// Flash-attention over 4096 keys per (b,n); key tile = one key row p (64 keys,
// shared emb_h[p]). Positional bias folded as biasH[p] + biasW[qw] per query.

#define NTHREADS 64

__global__ __launch_bounds__(NTHREADS) void abspos_attn_kernel(
    const float* __restrict__ Q, const float* __restrict__ K,
    const float* __restrict__ V, const float* __restrict__ EH,
    const float* __restrict__ EW, float* __restrict__ out)
{
    __shared__ float k_sm[64 * 32];      // K tile [key][dim]; also emb_h staging
    __shared__ float v_sm[64 * 32];      // V tile [key][dim]; also emb_w staging
    __shared__ float biasH[64 * 64];     // [p][query]  (thread reads own column)
    __shared__ float biasW[64 * 64];     // [qw][query]

    const int h   = blockIdx.x;   // query row
    const int bn  = blockIdx.y;   // b*8 + n
    const int b   = bn >> 3;
    const int n   = bn & 7;
    const int tid = threadIdx.x;  // query col (w)

    const float scale = 0.17677669529663688f;  // 32^-0.5

    // ---- load this thread's query, pre-scaled ----
    const float* qptr = Q + ((((size_t)bn * 64) + h) * 64 + tid) * 32;
    float q[32];
    #pragma unroll
    for (int d4 = 0; d4 < 8; d4++) {
        float4 t = ((const float4*)qptr)[d4];
        q[4*d4+0] = t.x * scale;
        q[4*d4+1] = t.y * scale;
        q[4*d4+2] = t.z * scale;
        q[4*d4+3] = t.w * scale;
    }

    // ---- stage embeddings in (aliased) smem, compute positional biases ----
    {
        const float4* eh4 = (const float4*)EH;
        const float4* ew4 = (const float4*)EW;
        float4* k4 = (float4*)k_sm;
        float4* v4 = (float4*)v_sm;
        #pragma unroll
        for (int it = 0; it < 8; it++) {       // 64*32 floats = 512 float4
            k4[it * 64 + tid] = eh4[it * 64 + tid];
            v4[it * 64 + tid] = ew4[it * 64 + tid];
        }
    }
    __syncthreads();
    for (int p = 0; p < 64; p++) {
        float sh = 0.f, sw = 0.f;
        #pragma unroll
        for (int d = 0; d < 32; d++) {
            sh += q[d] * k_sm[p * 32 + d];      // broadcast reads
            sw += q[d] * v_sm[p * 32 + d];
        }
        biasH[p * 64 + tid] = sh;               // conflict-free column writes
        biasW[p * 64 + tid] = sw;
    }
    // Each thread only reads its own biasH/biasW column; no sync needed for
    // the bias itself. The sync at loop top below protects emb->K tile reuse.

    // ---- online softmax state (log2-domain exp: exp(x) = exp2(x*log2e)) ----
    const float LOG2E = 1.4426950408889634f;
    float m = -INFINITY, l = 0.f;
    float o[32];
    #pragma unroll
    for (int d = 0; d < 32; d++) o[d] = 0.f;

    const float* Kb = K + (size_t)bn * 64 * 64 * 32;
    const float* Vb = V + (size_t)bn * 64 * 64 * 32;

    for (int p = 0; p < 64; p++) {
        __syncthreads();   // previous tile (or emb staging) fully consumed
        {
            const float4* kg = (const float4*)(Kb + p * 2048);
            const float4* vg = (const float4*)(Vb + p * 2048);
            float4* k4 = (float4*)k_sm;
            float4* v4 = (float4*)v_sm;
            #pragma unroll
            for (int it = 0; it < 8; it++) {
                k4[it * 64 + tid] = kg[it * 64 + tid];
                v4[it * 64 + tid] = vg[it * 64 + tid];
            }
        }
        __syncthreads();

        const float bh = biasH[p * 64 + tid];
        float s[64];
        float tmax = -INFINITY;
        #pragma unroll 8
        for (int j = 0; j < 64; j++) {
            float acc = bh + biasW[j * 64 + tid];
            const float4* kr = (const float4*)(k_sm + j * 32);
            #pragma unroll
            for (int d4 = 0; d4 < 8; d4++) {
                float4 kv = kr[d4];                 // broadcast across warp
                acc += q[4*d4+0] * kv.x;
                acc += q[4*d4+1] * kv.y;
                acc += q[4*d4+2] * kv.z;
                acc += q[4*d4+3] * kv.w;
            }
            s[j] = acc;
            tmax = fmaxf(tmax, acc);
        }

        const float mnew = fmaxf(m, tmax);
        const float corr = exp2f((m - mnew) * LOG2E);
        const float ml2  = mnew * LOG2E;
        l *= corr;
        #pragma unroll
        for (int d = 0; d < 32; d++) o[d] *= corr;

        #pragma unroll 8
        for (int j = 0; j < 64; j++) {
            const float pj = exp2f(fmaf(s[j], LOG2E, -ml2));
            l += pj;
            const float4* vr = (const float4*)(v_sm + j * 32);
            #pragma unroll
            for (int d4 = 0; d4 < 8; d4++) {
                float4 vv = vr[d4];
                o[4*d4+0] += pj * vv.x;
                o[4*d4+1] += pj * vv.y;
                o[4*d4+2] += pj * vv.z;
                o[4*d4+3] += pj * vv.w;
            }
        }
        m = mnew;
    }

    // ---- write out[b][h][w][n*32+d] ----
    const float inv = 1.f / l;
    float* op = out + (((size_t)b * 64 + h) * 64 + tid) * 256 + n * 32;
    #pragma unroll
    for (int d4 = 0; d4 < 8; d4++) {
        float4 t;
        t.x = o[4*d4+0] * inv;
        t.y = o[4*d4+1] * inv;
        t.z = o[4*d4+2] * inv;
        t.w = o[4*d4+3] * inv;
        ((float4*)op)[d4] = t;
    }
}

extern "C" void kernel_launch(void* const* d_in, const int* in_sizes, int n_in,
                              void* d_out, int out_size) {
    const float* q  = (const float*)d_in[0];
    const float* k  = (const float*)d_in[1];
    const float* v  = (const float*)d_in[2];
    const float* eh = (const float*)d_in[3];
    const float* ew = (const float*)d_in[4];
    dim3 grid(64, 16);   // (query row h) x (b*heads)
    abspos_attn_kernel<<<grid, NTHREADS>>>(q, k, v, eh, ew, (float*)d_out);
}

// round 5
// speedup vs baseline: 1.4573x; 1.4573x over previous
#include <cuda_runtime.h>
#include <math.h>

// AbsPosSelfAttention: q,k,v [2,8,64,64,32] fp32; emb_h,emb_w [64,32].
// out [2,64,64, 8*32] fp32 (out[b][h][w][n*32+d]).
//
// Step 1 (prep): K'[bn,p,j,d] = K[bn,p,j,d] + emb_h[p,d] + emb_w[j,d]
//   -> positional bias folded into keys; attention becomes pure q.k'.
// Step 2 (attn): flash attention, 2 query rows per CTA, 1 (w, 2 rows) pair
//   per thread. f32x2 packed FMA along d. exp2-domain softmax with lazy max.

#define NTH 64

__device__ float g_kp[2 * 8 * 64 * 64 * 32];   // 8.4 MB scratch

// ---------------- helpers ----------------
__device__ __forceinline__ unsigned long long pk2(float lo, float hi) {
    unsigned long long r;
    asm("mov.b64 %0, {%1, %2};" : "=l"(r) : "f"(lo), "f"(hi));
    return r;
}
__device__ __forceinline__ void up2(unsigned long long v, float& lo, float& hi) {
    asm("mov.b64 {%0, %1}, %2;" : "=f"(lo), "=f"(hi) : "l"(v));
}
#define FMA2(d, a, b, c) \
    asm("fma.rn.f32x2 %0, %1, %2, %3;" : "=l"(d) : "l"(a), "l"(b), "l"(c))
#define ADD2(d, a, b) \
    asm("add.rn.f32x2 %0, %1, %2;" : "=l"(d) : "l"(a), "l"(b))
#define MUL2(d, a, b) \
    asm("mul.rn.f32x2 %0, %1, %2;" : "=l"(d) : "l"(a), "l"(b))
__device__ __forceinline__ float ex2(float x) {
    float r;
    asm("ex2.approx.f32 %0, %1;" : "=f"(r) : "f"(x));
    return r;
}
__device__ __forceinline__ void cpa16(unsigned s, const void* g) {
    asm volatile("cp.async.cg.shared.global [%0], [%1], 16;\n" :: "r"(s), "l"(g));
}

// ---------------- prep: K' = K + emb_h + emb_w ----------------
__global__ void prep_kernel(const float* __restrict__ K,
                            const float* __restrict__ EH,
                            const float* __restrict__ EW) {
    int idx = blockIdx.x * blockDim.x + threadIdx.x;   // float4 index, 524288 total
    int d4 = idx & 7;
    int j  = (idx >> 3) & 63;
    int p  = (idx >> 9) & 63;
    float4 k  = ((const float4*)K)[idx];
    float4 eh = ((const float4*)EH)[p * 8 + d4];
    float4 ew = ((const float4*)EW)[j * 8 + d4];
    float4 o;
    o.x = k.x + eh.x + ew.x;
    o.y = k.y + eh.y + ew.y;
    o.z = k.z + eh.z + ew.z;
    o.w = k.w + eh.w + ew.w;
    ((float4*)g_kp)[idx] = o;
}

// ---------------- main attention ----------------
__global__ __launch_bounds__(NTH) void attn_kernel(
    const float* __restrict__ Q, const float* __restrict__ V,
    float* __restrict__ out)
{
    __shared__ float kbuf[2][64 * 32];
    __shared__ float vbuf[2][64 * 32];

    const int tid = threadIdx.x;               // query col w
    const int bn  = blockIdx.y;                // b*8+n
    const int b   = bn >> 3;
    const int n   = bn & 7;
    const int h0  = blockIdx.x * 2;            // two query rows per CTA
    const int h1  = h0 + 1;

    // fold attention scale AND log2(e) into q -> logits land in exp2 domain
    const float SC = 0.17677669529663688f * 1.4426950408889634f;

    unsigned long long qa[16], qb[16], oa[16], ob[16];
    {
        const float4* qp = (const float4*)(Q + (((size_t)bn * 64 + h0) * 64 + tid) * 32);
        #pragma unroll
        for (int i = 0; i < 8; i++) {
            float4 t = qp[i];
            qa[2 * i]     = pk2(t.x * SC, t.y * SC);
            qa[2 * i + 1] = pk2(t.z * SC, t.w * SC);
        }
    }
    {
        const float4* qp = (const float4*)(Q + (((size_t)bn * 64 + h1) * 64 + tid) * 32);
        #pragma unroll
        for (int i = 0; i < 8; i++) {
            float4 t = qp[i];
            qb[2 * i]     = pk2(t.x * SC, t.y * SC);
            qb[2 * i + 1] = pk2(t.z * SC, t.w * SC);
        }
    }
    #pragma unroll
    for (int i = 0; i < 16; i++) { oa[i] = 0ull; ob[i] = 0ull; }

    float m_a = 0.f, m_b = 0.f, l_a = 0.f, l_b = 0.f;   // log2-domain running max

    const float* Kp = g_kp + ((size_t)bn << 17);        // 64*64*32 per bn
    const float* Vb = V    + ((size_t)bn << 17);

    unsigned ks[2], vs[2];
    ks[0] = (unsigned)__cvta_generic_to_shared(kbuf[0]);
    ks[1] = (unsigned)__cvta_generic_to_shared(kbuf[1]);
    vs[0] = (unsigned)__cvta_generic_to_shared(vbuf[0]);
    vs[1] = (unsigned)__cvta_generic_to_shared(vbuf[1]);

    auto pref = [&](int p, int buf) {
        const float4* kg = (const float4*)(Kp + p * 2048);
        const float4* vg = (const float4*)(Vb + p * 2048);
        #pragma unroll
        for (int it = 0; it < 8; it++) {
            unsigned off = (unsigned)(it * 64 + tid) * 16u;
            cpa16(ks[buf] + off, kg + it * 64 + tid);
            cpa16(vs[buf] + off, vg + it * 64 + tid);
        }
    };

    pref(0, 0);
    asm volatile("cp.async.commit_group;\n");

    for (int p = 0; p < 64; p++) {
        const int cur = p & 1;
        if (p < 63) {
            pref(p + 1, cur ^ 1);
            asm volatile("cp.async.commit_group;\n");
            asm volatile("cp.async.wait_group 1;\n");
        } else {
            asm volatile("cp.async.wait_group 0;\n");
        }
        __syncthreads();   // tile p visible to all warps

        const float* kb = kbuf[cur];
        const float* vb = vbuf[cur];
        float tmax_a = -1e30f, tmax_b = -1e30f;

        #pragma unroll 4
        for (int j = 0; j < 64; j++) {
            const ulonglong2* kr = (const ulonglong2*)(kb + j * 32);
            unsigned long long a0 = 0ull, a1 = 0ull, b0 = 0ull, b1 = 0ull;
            #pragma unroll
            for (int i = 0; i < 4; i++) {
                ulonglong2 k0 = kr[2 * i];
                ulonglong2 k1 = kr[2 * i + 1];
                FMA2(a0, qa[4 * i + 0], k0.x, a0);
                FMA2(a0, qa[4 * i + 1], k0.y, a0);
                FMA2(a1, qa[4 * i + 2], k1.x, a1);
                FMA2(a1, qa[4 * i + 3], k1.y, a1);
                FMA2(b0, qb[4 * i + 0], k0.x, b0);
                FMA2(b0, qb[4 * i + 1], k0.y, b0);
                FMA2(b1, qb[4 * i + 2], k1.x, b1);
                FMA2(b1, qb[4 * i + 3], k1.y, b1);
            }
            unsigned long long af, bf;
            ADD2(af, a0, a1);
            ADD2(bf, b0, b1);
            float ax, ay, bx, by;
            up2(af, ax, ay);
            up2(bf, bx, by);
            const float s_a = ax + ay;          // logit * log2(e)
            const float s_b = bx + by;
            tmax_a = fmaxf(tmax_a, s_a);
            tmax_b = fmaxf(tmax_b, s_b);
            const float p_a = ex2(s_a - m_a);
            const float p_b = ex2(s_b - m_b);
            l_a += p_a;
            l_b += p_b;
            const unsigned long long pa2 = pk2(p_a, p_a);
            const unsigned long long pb2 = pk2(p_b, p_b);
            const ulonglong2* vr = (const ulonglong2*)(vb + j * 32);
            #pragma unroll
            for (int i = 0; i < 8; i++) {
                ulonglong2 vv = vr[i];
                FMA2(oa[2 * i],     pa2, vv.x, oa[2 * i]);
                FMA2(oa[2 * i + 1], pa2, vv.y, oa[2 * i + 1]);
                FMA2(ob[2 * i],     pb2, vv.x, ob[2 * i]);
                FMA2(ob[2 * i + 1], pb2, vv.y, ob[2 * i + 1]);
            }
        }

        // lazy max rescale (exact no-op when max unchanged: ex2(0)=1)
        {
            const float na = fmaxf(m_a, tmax_a);
            const float ca = ex2(m_a - na);
            l_a *= ca;
            const unsigned long long c2 = pk2(ca, ca);
            #pragma unroll
            for (int i = 0; i < 16; i++) MUL2(oa[i], oa[i], c2);
            m_a = na;
        }
        {
            const float nb = fmaxf(m_b, tmax_b);
            const float cb = ex2(m_b - nb);
            l_b *= cb;
            const unsigned long long c2 = pk2(cb, cb);
            #pragma unroll
            for (int i = 0; i < 16; i++) MUL2(ob[i], ob[i], c2);
            m_b = nb;
        }
        __syncthreads();   // everyone done with tile p before its buffer is re-filled
    }

    // ---- write out[b][h][w][n*32+d] ----
    {
        const float inv = 1.f / l_a;
        float* op = out + (((size_t)b * 64 + h0) * 64 + tid) * 256 + n * 32;
        #pragma unroll
        for (int i = 0; i < 8; i++) {
            float x0, x1, x2, x3;
            up2(oa[2 * i], x0, x1);
            up2(oa[2 * i + 1], x2, x3);
            float4 t;
            t.x = x0 * inv; t.y = x1 * inv; t.z = x2 * inv; t.w = x3 * inv;
            ((float4*)op)[i] = t;
        }
    }
    {
        const float inv = 1.f / l_b;
        float* op = out + (((size_t)b * 64 + h1) * 64 + tid) * 256 + n * 32;
        #pragma unroll
        for (int i = 0; i < 8; i++) {
            float x0, x1, x2, x3;
            up2(ob[2 * i], x0, x1);
            up2(ob[2 * i + 1], x2, x3);
            float4 t;
            t.x = x0 * inv; t.y = x1 * inv; t.z = x2 * inv; t.w = x3 * inv;
            ((float4*)op)[i] = t;
        }
    }
}

extern "C" void kernel_launch(void* const* d_in, const int* in_sizes, int n_in,
                              void* d_out, int out_size) {
    const float* q  = (const float*)d_in[0];
    const float* k  = (const float*)d_in[1];
    const float* v  = (const float*)d_in[2];
    const float* eh = (const float*)d_in[3];
    const float* ew = (const float*)d_in[4];

    prep_kernel<<<2048, 256>>>(k, eh, ew);
    dim3 grid(32, 16);   // (query-row pair) x (b*heads)
    attn_kernel<<<grid, NTH>>>(q, v, (float*)d_out);
}